// round 8
// baseline (speedup 1.0000x reference)
#include <cuda_runtime.h>
#include <cuda_fp16.h>

#define NQ      10000
#define D       128
#define NHEADS  8
#define NPOINTS 4
#define HSP     51
#define WSP     102
#define HW      (HSP * WSP)
#define NL      50
#define HD      16
#define TPB     256
#define GRID    592

// Scratch (device globals; no allocation allowed).
__device__ __align__(128) __half g_projh[NHEADS * HW * HD];  // fp16 table 1.33MB
__device__ float g_G[NHEADS * HW];    // fp32 scalar field, COLUMN-major [h][x*51+y]
__device__ unsigned g_arrive = 0;
__device__ unsigned g_depart = 0;

// ---------------------------------------------------------------------------
__global__ void __launch_bounds__(TPB, 4)
fused_kernel(const float* __restrict__ query,
             const float* __restrict__ value,
             const float* __restrict__ ref,
             const float* __restrict__ W_off,
             const float* __restrict__ b_off,
             const float* __restrict__ W_attn,
             const float* __restrict__ b_attn,
             const float* __restrict__ W_val,
             const float* __restrict__ b_val,
             const float* __restrict__ W_out,
             const float* __restrict__ b_out,
             const float* __restrict__ W_proj,
             float* __restrict__ out,
             float* __restrict__ out_idx,
             int n_idx,
             float* __restrict__ tailp,
             int tail_n) {
    __shared__ float s_msda[NL * D];      // 25.6 KB
    __shared__ float s_gcol[64 * 52];     // 13.3 KB staged G columns
    __shared__ float s_q[D];
    __shared__ float s_avg[D];
    __shared__ float s_off[64];           // pre-normalized offsets (x,y per h,p)
    __shared__ float s_aw[32];            // point softmax weights
    __shared__ float s_wp[D];             // W_out @ W_proj
    __shared__ float s_wts[64];           // level weights
    __shared__ float s_refy[NL];
    __shared__ float s_refx;
    __shared__ float s_part[D];
    __shared__ float s_wx[64];            // masked x-corner weights per (h,p)
    __shared__ int   s_cx[64];            // clamped x-corner coords per (h,p)
    __shared__ float s_lg[NL * 9];        // per-(l,h) logit partials, pad 9
    __shared__ float s_val[2 * D];        // phase-0 staging

    const __half* __restrict__ proj = g_projh;
    int tid = threadIdx.x;

    // ===================== wp = W_out @ W_proj (needed in phase 0) ==========
    {
        if (tid < D) s_avg[tid] = W_proj[tid];
        __syncthreads();
        int warp = tid >> 5, lane = tid & 31;
        for (int r = warp; r < D; r += 8) {
            float a = 0.f;
#pragma unroll
            for (int kk = 0; kk < 4; kk++) {
                int k = lane + kk * 32;
                a = fmaf(W_out[r * D + k], s_avg[k], a);
            }
#pragma unroll
            for (int o = 16; o; o >>= 1)
                a += __shfl_down_sync(0xffffffffu, a, o);
            if (lane == 0) s_wp[r] = a;
        }
        __syncthreads();
    }

    // ===================== phase 0: value projection (fp32->fp16 + G) =======
    {
        int ch = tid & 127;
        int half_ = tid >> 7;
        float wpc = s_wp[ch];
        for (int s0 = blockIdx.x * 2; s0 < HW; s0 += GRID * 2) {
            int s = s0 + half_;
            bool ok = s < HW;
            __syncthreads();
            if (ok) s_val[half_ * D + ch] = value[s * D + ch];
            __syncthreads();
            float acc = 0.f;
            if (ok) {
                acc = b_val[ch];
                const float* vr = &s_val[half_ * D];
#pragma unroll 8
                for (int k = 0; k < D; k++)
                    acc = fmaf(vr[k], W_val[k * D + ch], acc);
                g_projh[(ch >> 4) * (HW * HD) + s * HD + (ch & 15)] =
                    __float2half(acc);
            }
            // fp32 scalar field G[h][x][y] = sum_c proj_fp32 * wp (16-lane red.)
            float gterm = acc * wpc;
#pragma unroll
            for (int o = 1; o < 16; o <<= 1)
                gterm += __shfl_xor_sync(0xffffffffu, gterm, o);
            if (ok && (tid & 15) == 0) {
                int y = s / WSP;
                int x = s - y * WSP;
                g_G[(ch >> 4) * HW + x * HSP + y] = gterm;   // column-major
            }
        }
        for (int i = blockIdx.x * TPB + tid; i < tail_n; i += GRID * TPB)
            tailp[i] = 0.f;
    }

    // ===================== device-wide barrier ==============================
    __syncthreads();
    if (tid == 0) {
        __threadfence();
        atomicAdd(&g_arrive, 1u);
        while (*(volatile unsigned*)&g_arrive < GRID) { }
        __threadfence();
        unsigned old = atomicAdd(&g_depart, 1u);
        if (old == GRID - 1) {
            *(volatile unsigned*)&g_arrive = 0u;
            __threadfence();
            *(volatile unsigned*)&g_depart = 0u;
        }
    }
    __syncthreads();

    // ===================== phase 1: per-query attention =====================
    for (int q = blockIdx.x; q < NQ; q += GRID) {
        __syncthreads();
        if (tid < D) s_q[tid] = query[q * D + tid];
        __syncthreads();

        // ---- offsets (64) + attn logits (32): 192-thread k-split GEMV;
        //      warps 6-7 load ref y per level (+ the z-invariant x)
        if (tid < 192) {
            int col = tid >> 1;
            int half_ = tid & 1;
            bool is_off = col < 64;
            const float* W = is_off ? (W_off + col) : (W_attn + (col - 64));
            int stride = is_off ? 64 : 32;
            float acc = 0.f;
            if (half_ == 0)
                acc = is_off ? b_off[col] : b_attn[col - 64];
            int k0 = half_ * 64;
#pragma unroll 8
            for (int k = 0; k < 64; k++)
                acc = fmaf(s_q[k0 + k], W[(k0 + k) * stride], acc);
            acc += __shfl_xor_sync(0xffffffffu, acc, 1);
            if (half_ == 0) {
                if (is_off)
                    s_off[col] = acc / ((col & 1) ? (float)HSP : (float)WSP);
                else
                    s_aw[col - 64] = acc;
            }
        } else {
            int i = tid - 192;
            if (i < NL)
                s_refy[i] = ref[i * (NQ * 2) + q * 2 + 1];
            else if (i == NL)
                s_refx = ref[q * 2 + 0];
        }
        __syncthreads();

        // ---- point softmax (tid<8) + per-(h,p) x precompute (tid 32..63)
        if (tid < NHEADS) {
            float m = s_aw[tid * 4];
#pragma unroll
            for (int p = 1; p < 4; p++) m = fmaxf(m, s_aw[tid * 4 + p]);
            float e[4]; float ssum = 0.f;
#pragma unroll
            for (int p = 0; p < 4; p++) {
                e[p] = expf(s_aw[tid * 4 + p] - m);
                ssum += e[p];
            }
            float inv = 1.f / ssum;
#pragma unroll
            for (int p = 0; p < 4; p++) s_aw[tid * 4 + p] = e[p] * inv;
        } else if (tid >= 32 && tid < 64) {
            int up = tid - 32;
            float px = (s_refx + s_off[up * 2]) * (float)WSP - 0.5f;
            float x0f = floorf(px);
            float dx = px - x0f;
            int x0 = (int)x0f;
            s_wx[up * 2 + 0] = ((unsigned)x0 < WSP) ? (1.f - dx) : 0.f;
            s_wx[up * 2 + 1] = ((unsigned)(x0 + 1) < WSP) ? dx : 0.f;
            s_cx[up * 2 + 0] = min(max(x0, 0), WSP - 1);
            s_cx[up * 2 + 1] = min(max(x0 + 1, 0), WSP - 1);
        }
        __syncthreads();

        // ---- stage the 64 needed G columns (level-invariant x) into smem.
        //      Column c <-> (h,p,xcorner): coalesced 51-float contiguous loads.
        for (int i = tid; i < 64 * 52; i += TPB) {
            int c = i / 52;
            int y = i - c * 52;
            if (y < HSP) {
                int h = c >> 3;
                const float* colp = g_G + h * HW + s_cx[c] * HSP;
                s_gcol[c * 52 + y] = colp[y];
            }
        }
        __syncthreads();

        // ---- MSDA sampling: unit = (level, head), 4 lanes per unit.
        //      lane bits: bit1 = x-corner, bit0 = channel octet (8 ch).
        //      Lane j also samples staged G (smem) for point p==j: exact fp32
        //      logit path; fp16 only feeds the bev output.
        {
            int j = tid & 3;
            int slot = tid >> 2;             // 0..63
            int xc = j >> 1;
            int co = (j & 1) * 8;            // channel octet offset (halves)
            for (int u = slot; u < NL * NHEADS; u += 64) {
                int l = u >> 3, h = u & 7;
                float ry = s_refy[l];
                const __half* basep = proj + h * (HW * HD) + co;
                __half2 ac0 = __float2half2_rn(0.f);
                __half2 ac1 = ac0, ac2 = ac0, ac3 = ac0;
                float gdot = 0.f;
#pragma unroll
                for (int p = 0; p < NPOINTS; p++) {
                    int up = h * 4 + p;
                    float py = (ry + s_off[up * 2 + 1]) * (float)HSP - 0.5f;
                    float y0f = floorf(py);
                    float dy = py - y0f;
                    int y0 = (int)y0f;
                    float wy0 = ((unsigned)y0 < HSP) ? (1.f - dy) : 0.f;
                    float wy1 = ((unsigned)(y0 + 1) < HSP) ? dy : 0.f;
                    int cy0 = min(max(y0, 0), HSP - 1);
                    int cy1 = min(max(y0 + 1, 0), HSP - 1);
                    float waw = s_wx[up * 2 + xc] * s_aw[up];
                    int xcoord = s_cx[up * 2 + xc];
                    const uint4* r0 = (const uint4*)(basep + (cy0 * WSP + xcoord) * HD);
                    const uint4* r1 = (const uint4*)(basep + (cy1 * WSP + xcoord) * HD);
                    uint4 v0 = *r0;
                    uint4 v1 = *r1;
                    __half2 w0 = __float2half2_rn(waw * wy0);
                    __half2 w1 = __float2half2_rn(waw * wy1);
                    ac0 = __hfma2(*(__half2*)&v0.x, w0, ac0);
                    ac1 = __hfma2(*(__half2*)&v0.y, w0, ac1);
                    ac2 = __hfma2(*(__half2*)&v0.z, w0, ac2);
                    ac3 = __hfma2(*(__half2*)&v0.w, w0, ac3);
                    ac0 = __hfma2(*(__half2*)&v1.x, w1, ac0);
                    ac1 = __hfma2(*(__half2*)&v1.y, w1, ac1);
                    ac2 = __hfma2(*(__half2*)&v1.z, w1, ac2);
                    ac3 = __hfma2(*(__half2*)&v1.w, w1, ac3);
                    if (p == j) {
                        float wx0 = s_wx[up * 2 + 0];
                        float wx1 = s_wx[up * 2 + 1];
                        const float* c0p = &s_gcol[(up * 2 + 0) * 52];
                        const float* c1p = &s_gcol[(up * 2 + 1) * 52];
                        float g00 = c0p[cy0];
                        float g10 = c0p[cy1];
                        float g01 = c1p[cy0];
                        float g11 = c1p[cy1];
                        gdot = s_aw[up] * (wy0 * fmaf(wx0, g00, wx1 * g01)
                                         + wy1 * fmaf(wx0, g10, wx1 * g11));
                    }
                }
                // combine x-corner halves (lanes j and j^2)
                unsigned t;
                t = __shfl_xor_sync(0xffffffffu, *(unsigned*)&ac0, 2);
                ac0 = __hadd2(ac0, *(__half2*)&t);
                t = __shfl_xor_sync(0xffffffffu, *(unsigned*)&ac1, 2);
                ac1 = __hadd2(ac1, *(__half2*)&t);
                t = __shfl_xor_sync(0xffffffffu, *(unsigned*)&ac2, 2);
                ac2 = __hadd2(ac2, *(__half2*)&t);
                t = __shfl_xor_sync(0xffffffffu, *(unsigned*)&ac3, 2);
                ac3 = __hadd2(ac3, *(__half2*)&t);
                if (j < 2) {
                    float2 f0 = __half22float2(ac0);
                    float2 f1 = __half22float2(ac1);
                    float2 f2 = __half22float2(ac2);
                    float2 f3 = __half22float2(ac3);
                    int db = l * D + h * HD + co;
                    float4 w_;
                    w_.x = f0.x; w_.y = f0.y; w_.z = f1.x; w_.w = f1.y;
                    *(float4*)&s_msda[db] = w_;
                    float4 w2_;
                    w2_.x = f2.x; w2_.y = f2.y; w2_.z = f3.x; w2_.w = f3.y;
                    *(float4*)&s_msda[db + 4] = w2_;
                }
                // reduce fp32 logit partial over the 4 lanes (one point each)
                gdot += __shfl_xor_sync(0xffffffffu, gdot, 1);
                gdot += __shfl_xor_sync(0xffffffffu, gdot, 2);
                if (j == 0) s_lg[l * 9 + h] = gdot;
            }
        }
        __syncthreads();

        // ---- level softmax + argmax (warp 0; reduces 8 head-partials inline)
        if (tid < 32) {
            float v0 = -3.4e38f, v1 = -3.4e38f;
            if (tid < NL) {
                v0 = 0.f;
#pragma unroll
                for (int h = 0; h < NHEADS; h++) v0 += s_lg[tid * 9 + h];
            }
            if (tid + 32 < NL) {
                v1 = 0.f;
#pragma unroll
                for (int h = 0; h < NHEADS; h++) v1 += s_lg[(tid + 32) * 9 + h];
            }
            float bv; int bi;
            if (v1 > v0) { bv = v1; bi = tid + 32; }
            else         { bv = v0; bi = tid; }
#pragma unroll
            for (int o = 16; o; o >>= 1) {
                float ov = __shfl_down_sync(0xffffffffu, bv, o);
                int   oi = __shfl_down_sync(0xffffffffu, bi, o);
                if (ov > bv || (ov == bv && oi < bi)) { bv = ov; bi = oi; }
            }
            bv = __shfl_sync(0xffffffffu, bv, 0);
            float e0 = (tid < NL) ? expf(v0 - bv) : 0.f;
            float e1 = (tid + 32 < NL) ? expf(v1 - bv) : 0.f;
            float ssum = e0 + e1;
#pragma unroll
            for (int o = 16; o; o >>= 1)
                ssum += __shfl_xor_sync(0xffffffffu, ssum, o);
            float inv = 1.f / ssum;
            if (tid < NL) s_wts[tid] = e0 * inv;
            if (tid + 32 < NL) s_wts[tid + 32] = e1 * inv;
            if (tid == 0 && q < n_idx) out_idx[q] = (float)bi;
        }
        __syncthreads();

        // ---- weighted average over levels
        if (tid < D) {
            float acc = 0.f;
#pragma unroll 5
            for (int l = 0; l < NL; l++)
                acc = fmaf(s_wts[l], s_msda[l * D + tid], acc);
            s_avg[tid] = acc;
        }
        __syncthreads();

        // ---- final: out = avg @ W_out + b_out + 2*query  (k-split, 256 thr)
        {
            int ch = tid & 127, half_ = tid >> 7;
            int k0 = half_ * 64;
            float acc = 0.f;
#pragma unroll 8
            for (int k = 0; k < 64; k++)
                acc = fmaf(s_avg[k0 + k], W_out[(k0 + k) * D + ch], acc);
            if (half_) s_part[ch] = acc;
            __syncthreads();
            if (!half_)
                out[q * D + ch] = acc + s_part[ch] + b_out[ch] + 2.0f * s_q[ch];
        }
    }
}

// ---------------------------------------------------------------------------
extern "C" void kernel_launch(void* const* d_in, const int* in_sizes, int n_in,
                              void* d_out, int out_size) {
    const float* query  = (const float*)d_in[0];
    const float* value  = (const float*)d_in[1];
    const float* refp   = (const float*)d_in[2];
    const float* W_off  = (const float*)d_in[3];
    const float* b_off  = (const float*)d_in[4];
    const float* W_attn = (const float*)d_in[5];
    const float* b_attn = (const float*)d_in[6];
    const float* W_val  = (const float*)d_in[7];
    const float* b_val  = (const float*)d_in[8];
    const float* W_out  = (const float*)d_in[9];
    const float* b_out  = (const float*)d_in[10];
    const float* W_proj = (const float*)d_in[11];
    // b_proj (d_in[12]) unused: constant shift is softmax/argmax-invariant.

    float* out = (float*)d_out;

    int n_idx = out_size - NQ * D;
    if (n_idx < 0) n_idx = 0;
    if (n_idx > NQ) n_idx = NQ;

    int tail_n = out_size - (NQ * D + NQ);
    float* tailp = out + NQ * D + NQ;
    if (tail_n < 0) { tail_n = 0; tailp = out; }

    fused_kernel<<<GRID, TPB>>>(query, value, refp, W_off, b_off,
                                W_attn, b_attn, W_val, b_val,
                                W_out, b_out, W_proj,
                                out, out + NQ * D, n_idx, tailp, tail_n);
}

// round 9
// speedup vs baseline: 1.5678x; 1.5678x over previous
#include <cuda_runtime.h>
#include <cuda_fp16.h>

#define NQ      10000
#define D       128
#define NHEADS  8
#define NPOINTS 4
#define HSP     51
#define WSP     102
#define HW      (HSP * WSP)
#define NL      50
#define HD      16
#define TPB     256
#define GRID    592

// Scratch (device globals; no allocation allowed).
__device__ __align__(128) __half g_projh[NHEADS * HW * HD];  // fp16 table 1.33MB
__device__ float g_G[NHEADS * HW];    // fp32 scalar field, row-major [h][y*W+x]
__device__ unsigned g_arrive = 0;
__device__ unsigned g_depart = 0;

// ---------------------------------------------------------------------------
__global__ void __launch_bounds__(TPB, 4)
fused_kernel(const float* __restrict__ query,
             const float* __restrict__ value,
             const float* __restrict__ ref,
             const float* __restrict__ W_off,
             const float* __restrict__ b_off,
             const float* __restrict__ W_attn,
             const float* __restrict__ b_attn,
             const float* __restrict__ W_val,
             const float* __restrict__ b_val,
             const float* __restrict__ W_out,
             const float* __restrict__ b_out,
             const float* __restrict__ W_proj,
             float* __restrict__ out,
             float* __restrict__ out_idx,
             int n_idx,
             float* __restrict__ tailp,
             int tail_n) {
    __shared__ float s_msda[NL * D];      // 25.6 KB
    __shared__ float s_q[D];
    __shared__ float s_avg[D];
    __shared__ float s_off[64];           // pre-normalized offsets (x,y per h,p)
    __shared__ float s_aw[32];            // point softmax weights
    __shared__ float s_wp[D];             // W_out @ W_proj
    __shared__ float s_wts[64];           // level weights
    __shared__ float s_refy[NL];
    __shared__ float s_refx;
    __shared__ float s_part[D];
    __shared__ float s_wx[64];            // masked x-corner weights per (h,p)
    __shared__ int   s_cx[64];            // clamped x-corner coords per (h,p)
    __shared__ float s_lg[NL];            // full fp32 level logits
    __shared__ float s_val[2 * D];        // phase-0 staging

    const __half* __restrict__ proj = g_projh;
    int tid = threadIdx.x;

    // ===================== wp = W_out @ W_proj (needed in phase 0) ==========
    {
        if (tid < D) s_avg[tid] = W_proj[tid];
        __syncthreads();
        int warp = tid >> 5, lane = tid & 31;
        for (int r = warp; r < D; r += 8) {
            float a = 0.f;
#pragma unroll
            for (int kk = 0; kk < 4; kk++) {
                int k = lane + kk * 32;
                a = fmaf(W_out[r * D + k], s_avg[k], a);
            }
#pragma unroll
            for (int o = 16; o; o >>= 1)
                a += __shfl_down_sync(0xffffffffu, a, o);
            if (lane == 0) s_wp[r] = a;
        }
        __syncthreads();
    }

    // ===================== phase 0: value projection (fp32->fp16 + G) =======
    {
        int ch = tid & 127;
        int half_ = tid >> 7;
        float wpc = s_wp[ch];
        for (int s0 = blockIdx.x * 2; s0 < HW; s0 += GRID * 2) {
            int s = s0 + half_;
            bool ok = s < HW;
            __syncthreads();
            if (ok) s_val[half_ * D + ch] = value[s * D + ch];
            __syncthreads();
            float acc = 0.f;
            if (ok) {
                acc = b_val[ch];
                const float* vr = &s_val[half_ * D];
#pragma unroll 8
                for (int k = 0; k < D; k++)
                    acc = fmaf(vr[k], W_val[k * D + ch], acc);
                g_projh[(ch >> 4) * (HW * HD) + s * HD + (ch & 15)] =
                    __float2half(acc);
            }
            // fp32 scalar field G[h][s] = sum_c proj_fp32 * wp (16-lane reduce)
            float gterm = acc * wpc;
#pragma unroll
            for (int o = 1; o < 16; o <<= 1)
                gterm += __shfl_xor_sync(0xffffffffu, gterm, o);
            if (ok && (tid & 15) == 0)
                g_G[(ch >> 4) * HW + s] = gterm;
        }
        for (int i = blockIdx.x * TPB + tid; i < tail_n; i += GRID * TPB)
            tailp[i] = 0.f;
    }

    // ===================== device-wide barrier ==============================
    __syncthreads();
    if (tid == 0) {
        __threadfence();
        atomicAdd(&g_arrive, 1u);
        while (*(volatile unsigned*)&g_arrive < GRID) { }
        __threadfence();
        unsigned old = atomicAdd(&g_depart, 1u);
        if (old == GRID - 1) {
            *(volatile unsigned*)&g_arrive = 0u;
            __threadfence();
            *(volatile unsigned*)&g_depart = 0u;
        }
    }
    __syncthreads();

    // ===================== phase 1: per-query attention =====================
    for (int q = blockIdx.x; q < NQ; q += GRID) {
        __syncthreads();
        if (tid < D) s_q[tid] = query[q * D + tid];
        __syncthreads();

        // ---- offsets (64) + attn logits (32): 192-thread k-split GEMV;
        //      warps 6-7 load ref y per level (+ the z-invariant x)
        if (tid < 192) {
            int col = tid >> 1;
            int half_ = tid & 1;
            bool is_off = col < 64;
            const float* W = is_off ? (W_off + col) : (W_attn + (col - 64));
            int stride = is_off ? 64 : 32;
            float acc = 0.f;
            if (half_ == 0)
                acc = is_off ? b_off[col] : b_attn[col - 64];
            int k0 = half_ * 64;
#pragma unroll 8
            for (int k = 0; k < 64; k++)
                acc = fmaf(s_q[k0 + k], W[(k0 + k) * stride], acc);
            acc += __shfl_xor_sync(0xffffffffu, acc, 1);
            if (half_ == 0) {
                if (is_off)
                    s_off[col] = acc / ((col & 1) ? (float)HSP : (float)WSP);
                else
                    s_aw[col - 64] = acc;
            }
        } else {
            int i = tid - 192;
            if (i < NL)
                s_refy[i] = ref[i * (NQ * 2) + q * 2 + 1];
            else if (i == NL)
                s_refx = ref[q * 2 + 0];
        }
        __syncthreads();

        // ---- point softmax (tid<8) + per-(h,p) x precompute (tid 32..63)
        if (tid < NHEADS) {
            float m = s_aw[tid * 4];
#pragma unroll
            for (int p = 1; p < 4; p++) m = fmaxf(m, s_aw[tid * 4 + p]);
            float e[4]; float ssum = 0.f;
#pragma unroll
            for (int p = 0; p < 4; p++) {
                e[p] = expf(s_aw[tid * 4 + p] - m);
                ssum += e[p];
            }
            float inv = 1.f / ssum;
#pragma unroll
            for (int p = 0; p < 4; p++) s_aw[tid * 4 + p] = e[p] * inv;
        } else if (tid >= 32 && tid < 64) {
            int up = tid - 32;
            float px = (s_refx + s_off[up * 2]) * (float)WSP - 0.5f;
            float x0f = floorf(px);
            float dx = px - x0f;
            int x0 = (int)x0f;
            s_wx[up * 2 + 0] = ((unsigned)x0 < WSP) ? (1.f - dx) : 0.f;
            s_wx[up * 2 + 1] = ((unsigned)(x0 + 1) < WSP) ? dx : 0.f;
            s_cx[up * 2 + 0] = min(max(x0, 0), WSP - 1);
            s_cx[up * 2 + 1] = min(max(x0 + 1, 0), WSP - 1);
        }
        __syncthreads();

        // ---- MSDA channel sampling (pure fp16): unit = (level, head),
        //      4 lanes per unit; lane bits: bit1 = x-corner, bit0 = chan octet.
        {
            int j = tid & 3;
            int slot = tid >> 2;             // 0..63
            int xc = j >> 1;
            int co = (j & 1) * 8;            // channel octet offset (halves)
            for (int u = slot; u < NL * NHEADS; u += 64) {
                int l = u >> 3, h = u & 7;
                float ry = s_refy[l];
                const __half* basep = proj + h * (HW * HD) + co;
                __half2 ac0 = __float2half2_rn(0.f);
                __half2 ac1 = ac0, ac2 = ac0, ac3 = ac0;
#pragma unroll
                for (int p = 0; p < NPOINTS; p++) {
                    int up = h * 4 + p;
                    float py = (ry + s_off[up * 2 + 1]) * (float)HSP - 0.5f;
                    float y0f = floorf(py);
                    float dy = py - y0f;
                    int y0 = (int)y0f;
                    float wy0 = ((unsigned)y0 < HSP) ? (1.f - dy) : 0.f;
                    float wy1 = ((unsigned)(y0 + 1) < HSP) ? dy : 0.f;
                    int cy0 = min(max(y0, 0), HSP - 1);
                    int cy1 = min(max(y0 + 1, 0), HSP - 1);
                    float waw = s_wx[up * 2 + xc] * s_aw[up];
                    int xcoord = s_cx[up * 2 + xc];
                    const uint4* r0 = (const uint4*)(basep + (cy0 * WSP + xcoord) * HD);
                    const uint4* r1 = (const uint4*)(basep + (cy1 * WSP + xcoord) * HD);
                    uint4 v0 = *r0;
                    uint4 v1 = *r1;
                    __half2 w0 = __float2half2_rn(waw * wy0);
                    __half2 w1 = __float2half2_rn(waw * wy1);
                    ac0 = __hfma2(*(__half2*)&v0.x, w0, ac0);
                    ac1 = __hfma2(*(__half2*)&v0.y, w0, ac1);
                    ac2 = __hfma2(*(__half2*)&v0.z, w0, ac2);
                    ac3 = __hfma2(*(__half2*)&v0.w, w0, ac3);
                    ac0 = __hfma2(*(__half2*)&v1.x, w1, ac0);
                    ac1 = __hfma2(*(__half2*)&v1.y, w1, ac1);
                    ac2 = __hfma2(*(__half2*)&v1.z, w1, ac2);
                    ac3 = __hfma2(*(__half2*)&v1.w, w1, ac3);
                }
                // combine x-corner halves (lanes j and j^2)
                unsigned t;
                t = __shfl_xor_sync(0xffffffffu, *(unsigned*)&ac0, 2);
                ac0 = __hadd2(ac0, *(__half2*)&t);
                t = __shfl_xor_sync(0xffffffffu, *(unsigned*)&ac1, 2);
                ac1 = __hadd2(ac1, *(__half2*)&t);
                t = __shfl_xor_sync(0xffffffffu, *(unsigned*)&ac2, 2);
                ac2 = __hadd2(ac2, *(__half2*)&t);
                t = __shfl_xor_sync(0xffffffffu, *(unsigned*)&ac3, 2);
                ac3 = __hadd2(ac3, *(__half2*)&t);
                if (j < 2) {
                    float2 f0 = __half22float2(ac0);
                    float2 f1 = __half22float2(ac1);
                    float2 f2 = __half22float2(ac2);
                    float2 f3 = __half22float2(ac3);
                    int db = l * D + h * HD + co;
                    float4 w_;
                    w_.x = f0.x; w_.y = f0.y; w_.z = f1.x; w_.w = f1.y;
                    *(float4*)&s_msda[db] = w_;
                    float4 w2_;
                    w2_.x = f2.x; w2_.y = f2.y; w2_.z = f3.x; w2_.w = f3.y;
                    *(float4*)&s_msda[db + 4] = w2_;
                }
            }

            // ---- exact fp32 level logits: warp = level, lane = (h,p).
            //      logit_l = sum_{h,p} aw * bilinear(G_h, loc). All 32 lanes
            //      active per load; x-pair corners share a cache line.
            int warp = tid >> 5;
            int lane = tid & 31;             // lane == up == h*4+p
            int h = lane >> 2;
            const float* Gh = g_G + h * HW;
            float wx0 = s_wx[lane * 2 + 0];
            float wx1 = s_wx[lane * 2 + 1];
            int cx0 = s_cx[lane * 2 + 0];
            int cx1 = s_cx[lane * 2 + 1];
            float offy = s_off[lane * 2 + 1];
            float awl = s_aw[lane];
            for (int l = warp; l < NL; l += 8) {
                float py = (s_refy[l] + offy) * (float)HSP - 0.5f;
                float y0f = floorf(py);
                float dy = py - y0f;
                int y0 = (int)y0f;
                float wy0 = ((unsigned)y0 < HSP) ? (1.f - dy) : 0.f;
                float wy1 = ((unsigned)(y0 + 1) < HSP) ? dy : 0.f;
                int cy0 = min(max(y0, 0), HSP - 1);
                int cy1 = min(max(y0 + 1, 0), HSP - 1);
                const float* r0 = Gh + cy0 * WSP;
                const float* r1 = Gh + cy1 * WSP;
                float g00 = r0[cx0], g01 = r0[cx1];
                float g10 = r1[cx0], g11 = r1[cx1];
                float t = awl * (wy0 * fmaf(wx0, g00, wx1 * g01)
                               + wy1 * fmaf(wx0, g10, wx1 * g11));
#pragma unroll
                for (int o = 16; o; o >>= 1)
                    t += __shfl_xor_sync(0xffffffffu, t, o);
                if (lane == 0) s_lg[l] = t;
            }
        }
        __syncthreads();

        // ---- level softmax + argmax: warp 0, parallel
        if (tid < 32) {
            float v0 = (tid < NL) ? s_lg[tid] : -3.4e38f;
            float v1 = (tid + 32 < NL) ? s_lg[tid + 32] : -3.4e38f;
            float bv; int bi;
            if (v1 > v0) { bv = v1; bi = tid + 32; }
            else         { bv = v0; bi = tid; }
#pragma unroll
            for (int o = 16; o; o >>= 1) {
                float ov = __shfl_down_sync(0xffffffffu, bv, o);
                int   oi = __shfl_down_sync(0xffffffffu, bi, o);
                if (ov > bv || (ov == bv && oi < bi)) { bv = ov; bi = oi; }
            }
            bv = __shfl_sync(0xffffffffu, bv, 0);
            float e0 = (tid < NL) ? expf(v0 - bv) : 0.f;
            float e1 = (tid + 32 < NL) ? expf(v1 - bv) : 0.f;
            float ssum = e0 + e1;
#pragma unroll
            for (int o = 16; o; o >>= 1)
                ssum += __shfl_xor_sync(0xffffffffu, ssum, o);
            float inv = 1.f / ssum;
            if (tid < NL) s_wts[tid] = e0 * inv;
            if (tid + 32 < NL) s_wts[tid + 32] = e1 * inv;
            if (tid == 0 && q < n_idx) out_idx[q] = (float)bi;
        }
        __syncthreads();

        // ---- weighted average over levels
        if (tid < D) {
            float acc = 0.f;
#pragma unroll 5
            for (int l = 0; l < NL; l++)
                acc = fmaf(s_wts[l], s_msda[l * D + tid], acc);
            s_avg[tid] = acc;
        }
        __syncthreads();

        // ---- final: out = avg @ W_out + b_out + 2*query  (k-split, 256 thr)
        {
            int ch = tid & 127, half_ = tid >> 7;
            int k0 = half_ * 64;
            float acc = 0.f;
#pragma unroll 8
            for (int k = 0; k < 64; k++)
                acc = fmaf(s_avg[k0 + k], W_out[(k0 + k) * D + ch], acc);
            if (half_) s_part[ch] = acc;
            __syncthreads();
            if (!half_)
                out[q * D + ch] = acc + s_part[ch] + b_out[ch] + 2.0f * s_q[ch];
        }
    }
}

// ---------------------------------------------------------------------------
extern "C" void kernel_launch(void* const* d_in, const int* in_sizes, int n_in,
                              void* d_out, int out_size) {
    const float* query  = (const float*)d_in[0];
    const float* value  = (const float*)d_in[1];
    const float* refp   = (const float*)d_in[2];
    const float* W_off  = (const float*)d_in[3];
    const float* b_off  = (const float*)d_in[4];
    const float* W_attn = (const float*)d_in[5];
    const float* b_attn = (const float*)d_in[6];
    const float* W_val  = (const float*)d_in[7];
    const float* b_val  = (const float*)d_in[8];
    const float* W_out  = (const float*)d_in[9];
    const float* b_out  = (const float*)d_in[10];
    const float* W_proj = (const float*)d_in[11];
    // b_proj (d_in[12]) unused: constant shift is softmax/argmax-invariant.

    float* out = (float*)d_out;

    int n_idx = out_size - NQ * D;
    if (n_idx < 0) n_idx = 0;
    if (n_idx > NQ) n_idx = NQ;

    int tail_n = out_size - (NQ * D + NQ);
    float* tailp = out + NQ * D + NQ;
    if (tail_n < 0) { tail_n = 0; tailp = out; }

    fused_kernel<<<GRID, TPB>>>(query, value, refp, W_off, b_off,
                                W_attn, b_attn, W_val, b_val,
                                W_out, b_out, W_proj,
                                out, out + NQ * D, n_idx, tailp, tail_n);
}